// round 4
// baseline (speedup 1.0000x reference)
#include <cuda_runtime.h>

// WeightedMSELoss: pred/target [4096,1024,6] fp32.
// channels 0-2 = translation, 3-5 = rotation (angle-wrapped into (-pi,pi]).
// trans_loss = mean(trans_diff^2) * 1.0
// rot_loss   = mean(rot_diff^2)   * 100.0
// out = [total, trans, rot]  (3 fp32)

static constexpr int NB = 1024;   // blocks for partial kernel
static constexpr int NT = 256;    // threads per block

// Per-block partial sums (trans, rot). __device__ global: no allocation,
// written fresh every launch -> deterministic under graph replay.
__device__ double2 g_part[NB];

__device__ __forceinline__ float wrapa(float x) {
    // fp32-rounded pi and 2*pi, matching jnp float32 semantics
    const float PI     = 3.14159265358979323846f;
    const float TWO_PI = 6.28318530717958647692f;
    x = (x >  PI) ? x - TWO_PI : x;
    x = (x < -PI) ? x + TWO_PI : x;
    return x;
}

__global__ void __launch_bounds__(NT)
wmse_partial_kernel(const float4* __restrict__ pred,
                    const float4* __restrict__ tgt,
                    long long nvec) {
    long long tid    = (long long)blockIdx.x * NT + threadIdx.x;
    long long stride = (long long)NB * NT;

    float st = 0.0f;  // translation sum of squares
    float sr = 0.0f;  // rotation sum of squares

    #pragma unroll 4
    for (long long v = tid; v < nvec; v += stride) {
        float4 p = __ldg(&pred[v]);
        float4 t = __ldg(&tgt[v]);

        // channel of element 4v is (4v) mod 6, determined by r = v mod 3:
        //   r=0 -> 0,  r=1 -> 4,  r=2 -> 2
        int r  = (int)(v % 3);
        int c0 = (r == 0) ? 0 : ((r == 1) ? 4 : 2);

        float pcs[4] = {p.x, p.y, p.z, p.w};
        float tcs[4] = {t.x, t.y, t.z, t.w};

        #pragma unroll
        for (int j = 0; j < 4; j++) {
            int ch = c0 + j;
            ch -= (ch >= 6) ? 6 : 0;
            bool rot = (ch >= 3);
            float a = rot ? wrapa(pcs[j]) : pcs[j];
            float b = rot ? wrapa(tcs[j]) : tcs[j];
            float d  = a - b;
            float dd = d * d;
            if (rot) sr += dd; else st += dd;   // predicated, no divergence cost
        }
    }

    // warp reduce
    #pragma unroll
    for (int o = 16; o; o >>= 1) {
        st += __shfl_xor_sync(0xffffffffu, st, o);
        sr += __shfl_xor_sync(0xffffffffu, sr, o);
    }

    __shared__ float sst[NT / 32];
    __shared__ float ssr[NT / 32];
    int lane = threadIdx.x & 31;
    int w    = threadIdx.x >> 5;
    if (lane == 0) { sst[w] = st; ssr[w] = sr; }
    __syncthreads();

    if (w == 0) {
        st = (lane < NT / 32) ? sst[lane] : 0.0f;
        sr = (lane < NT / 32) ? ssr[lane] : 0.0f;
        #pragma unroll
        for (int o = 4; o; o >>= 1) {
            st += __shfl_xor_sync(0xffffffffu, st, o);
            sr += __shfl_xor_sync(0xffffffffu, sr, o);
        }
        if (lane == 0) g_part[blockIdx.x] = make_double2((double)st, (double)sr);
    }
}

__global__ void __launch_bounds__(256)
wmse_finalize_kernel(float* __restrict__ out, long long ntotal) {
    double st = 0.0, sr = 0.0;
    for (int i = threadIdx.x; i < NB; i += 256) {
        double2 p = g_part[i];
        st += p.x;
        sr += p.y;
    }
    #pragma unroll
    for (int o = 16; o; o >>= 1) {
        st += __shfl_xor_sync(0xffffffffu, st, o);
        sr += __shfl_xor_sync(0xffffffffu, sr, o);
    }
    __shared__ double sst[8];
    __shared__ double ssr[8];
    int lane = threadIdx.x & 31;
    int w    = threadIdx.x >> 5;
    if (lane == 0) { sst[w] = st; ssr[w] = sr; }
    __syncthreads();
    if (threadIdx.x == 0) {
        st = 0.0; sr = 0.0;
        #pragma unroll
        for (int i = 0; i < 8; i++) { st += sst[i]; sr += ssr[i]; }
        // per-type element count = ntotal / 2  (3 of 6 channels each)
        double cnt = (double)(ntotal / 2);
        double trans_loss = (st / cnt) * 1.0;
        double rot_loss   = (sr / cnt) * 100.0;
        out[0] = (float)(trans_loss + rot_loss);
        out[1] = (float)trans_loss;
        out[2] = (float)rot_loss;
    }
}

extern "C" void kernel_launch(void* const* d_in, const int* in_sizes, int n_in,
                              void* d_out, int out_size) {
    const float4* pred = (const float4*)d_in[0];
    const float4* tgt  = (const float4*)d_in[1];
    float* out = (float*)d_out;

    long long ntotal = (long long)in_sizes[0];   // 25,165,824 (divisible by 12)
    long long nvec   = ntotal / 4;

    wmse_partial_kernel<<<NB, NT>>>(pred, tgt, nvec);
    wmse_finalize_kernel<<<1, 256>>>(out, ntotal);
}

// round 6
// speedup vs baseline: 1.1510x; 1.1510x over previous
#include <cuda_runtime.h>

// WeightedMSELoss: pred/target [4096,1024,6] fp32.
// channels 0-2 = translation, 3-5 = rotation (angle-wrapped into (-pi,pi]).
// trans_loss = mean(trans_diff^2)*1 ; rot_loss = mean(rot_diff^2)*100
// out = [total, trans, rot]  (3 fp32)
//
// Single fused kernel: grid-wide partial sums + "last block" final reduction
// (threadfence + atomic ticket; ticket reset by last block -> graph-replay safe).

static constexpr int NB = 592;    // 148 SMs x 4 CTAs -> exactly one wave
static constexpr int NT = 256;

__device__ double2 g_part[NB];
__device__ unsigned int g_ticket;   // zero-init at load; last block resets to 0

__device__ __forceinline__ float wrapa(float x) {
    const float PI     = 3.14159265358979323846f;
    const float TWO_PI = 6.28318530717958647692f;
    x = (x >  PI) ? x - TWO_PI : x;
    x = (x < -PI) ? x + TWO_PI : x;
    return x;
}

__global__ void __launch_bounds__(NT)
wmse_fused_kernel(const float4* __restrict__ pred,
                  const float4* __restrict__ tgt,
                  float* __restrict__ out,
                  long long nvec, long long ntotal) {
    long long tid    = (long long)blockIdx.x * NT + threadIdx.x;
    long long stride = (long long)NB * NT;

    float st = 0.0f;  // translation sum of squares
    float sr = 0.0f;  // rotation sum of squares

    #pragma unroll 4
    for (long long v = tid; v < nvec; v += stride) {
        float4 p = __ldg(&pred[v]);
        float4 t = __ldg(&tgt[v]);

        // channel of element 4v is (4v) mod 6, determined by r = v mod 3:
        //   r=0 -> 0,  r=1 -> 4,  r=2 -> 2
        int r  = (int)(v % 3);
        int c0 = (r == 0) ? 0 : ((r == 1) ? 4 : 2);

        float pcs[4] = {p.x, p.y, p.z, p.w};
        float tcs[4] = {t.x, t.y, t.z, t.w};

        #pragma unroll
        for (int j = 0; j < 4; j++) {
            int ch = c0 + j;
            ch -= (ch >= 6) ? 6 : 0;
            bool rot = (ch >= 3);
            float a = rot ? wrapa(pcs[j]) : pcs[j];
            float b = rot ? wrapa(tcs[j]) : tcs[j];
            float d  = a - b;
            float dd = d * d;
            if (rot) sr += dd; else st += dd;   // predicated, no divergence
        }
    }

    // ---- intra-block reduce (fp32 partials, fixed order) ----
    #pragma unroll
    for (int o = 16; o; o >>= 1) {
        st += __shfl_xor_sync(0xffffffffu, st, o);
        sr += __shfl_xor_sync(0xffffffffu, sr, o);
    }

    __shared__ float sst[NT / 32];
    __shared__ float ssr[NT / 32];
    __shared__ bool  s_last;
    int lane = threadIdx.x & 31;
    int w    = threadIdx.x >> 5;
    if (lane == 0) { sst[w] = st; ssr[w] = sr; }
    __syncthreads();

    if (w == 0) {
        st = (lane < NT / 32) ? sst[lane] : 0.0f;
        sr = (lane < NT / 32) ? ssr[lane] : 0.0f;
        #pragma unroll
        for (int o = 4; o; o >>= 1) {
            st += __shfl_xor_sync(0xffffffffu, st, o);
            sr += __shfl_xor_sync(0xffffffffu, sr, o);
        }
        if (lane == 0) g_part[blockIdx.x] = make_double2((double)st, (double)sr);
    }

    // ---- last-block final reduction ----
    if (threadIdx.x == 0) {
        __threadfence();                              // publish g_part[bid]
        unsigned old = atomicAdd(&g_ticket, 1u);
        s_last = (old == (unsigned)(NB - 1));
    }
    __syncthreads();
    if (!s_last) return;

    if (threadIdx.x == 0) g_ticket = 0;               // reset for next replay

    double dst = 0.0, dsr = 0.0;
    for (int i = threadIdx.x; i < NB; i += NT) {
        double2 p = __ldcg(&g_part[i]);               // L2 load (bypass stale L1)
        dst += p.x;
        dsr += p.y;
    }
    #pragma unroll
    for (int o = 16; o; o >>= 1) {
        dst += __shfl_xor_sync(0xffffffffu, dst, o);
        dsr += __shfl_xor_sync(0xffffffffu, dsr, o);
    }
    __shared__ double dt[NT / 32];
    __shared__ double dr[NT / 32];
    if (lane == 0) { dt[w] = dst; dr[w] = dsr; }
    __syncthreads();
    if (threadIdx.x == 0) {
        dst = 0.0; dsr = 0.0;
        #pragma unroll
        for (int i = 0; i < NT / 32; i++) { dst += dt[i]; dsr += dr[i]; }
        double cnt = (double)(ntotal / 2);            // 3 of 6 channels each
        double trans_loss = dst / cnt;
        double rot_loss   = (dsr / cnt) * 100.0;
        out[0] = (float)(trans_loss + rot_loss);
        out[1] = (float)trans_loss;
        out[2] = (float)rot_loss;
    }
}

extern "C" void kernel_launch(void* const* d_in, const int* in_sizes, int n_in,
                              void* d_out, int out_size) {
    const float4* pred = (const float4*)d_in[0];
    const float4* tgt  = (const float4*)d_in[1];
    float* out = (float*)d_out;

    long long ntotal = (long long)in_sizes[0];   // 25,165,824 (divisible by 12)
    long long nvec   = ntotal / 4;

    wmse_fused_kernel<<<NB, NT>>>(pred, tgt, out, nvec, ntotal);
}

// round 7
// speedup vs baseline: 1.3038x; 1.1328x over previous
#include <cuda_runtime.h>

// WeightedMSELoss: pred/target [4096,1024,6] fp32.
// channels 0-2 = translation, 3-5 = rotation (angle-wrapped into (-pi,pi]).
// trans_loss = mean(trans_diff^2)*1 ; rot_loss = mean(rot_diff^2)*100
// out = [total, trans, rot]  (3 fp32)
//
// Each thread processes aligned groups of 3 float4s = 12 floats = exactly 2
// channel periods -> rot/trans classification is COMPILE-TIME (zero per-iter
// classification ALU). Fused last-block final reduction (atomic ticket,
// reset for graph-replay determinism).

static constexpr int NB = 740;    // 148 SMs x 5 CTAs -> exactly one wave
static constexpr int NT = 256;

__device__ double2 g_part[NB];
__device__ unsigned int g_ticket;   // zero-init at load; last block resets

__device__ __forceinline__ float wrapa(float x) {
    const float PI     = 3.14159265358979323846f;
    const float TWO_PI = 6.28318530717958647692f;
    x = (x >  PI) ? x - TWO_PI : x;
    x = (x < -PI) ? x + TWO_PI : x;
    return x;
}

__global__ void __launch_bounds__(NT, 5)
wmse_fused_kernel(const float4* __restrict__ pred,
                  const float4* __restrict__ tgt,
                  float* __restrict__ out,
                  int ngroups, long long ntotal) {
    int tid    = blockIdx.x * NT + threadIdx.x;
    int stride = NB * NT;

    float st = 0.0f;  // translation sum of squares
    float sr = 0.0f;  // rotation sum of squares

    for (int g = tid; g < ngroups; g += stride) {
        const float4* pp = pred + 3 * g;
        const float4* tp = tgt  + 3 * g;
        float4 p0 = __ldg(pp + 0);
        float4 p1 = __ldg(pp + 1);
        float4 p2 = __ldg(pp + 2);
        float4 t0 = __ldg(tp + 0);
        float4 t1 = __ldg(tp + 1);
        float4 t2 = __ldg(tp + 2);

        // channels of the 12 floats: 0,1,2,3, 4,5,0,1, 2,3,4,5
        // trans (ch<3): p0.xyz, p1.zw, p2.x   rot (ch>=3): p0.w, p1.xy, p2.yzw
        #define TRS(a, b) { float d_ = (a) - (b); st = fmaf(d_, d_, st); }
        #define ROT(a, b) { float d_ = wrapa(a) - wrapa(b); sr = fmaf(d_, d_, sr); }
        TRS(p0.x, t0.x); TRS(p0.y, t0.y); TRS(p0.z, t0.z); ROT(p0.w, t0.w);
        ROT(p1.x, t1.x); ROT(p1.y, t1.y); TRS(p1.z, t1.z); TRS(p1.w, t1.w);
        TRS(p2.x, t2.x); ROT(p2.y, t2.y); ROT(p2.z, t2.z); ROT(p2.w, t2.w);
        #undef TRS
        #undef ROT
    }

    // ---- intra-block reduce (fp32 partials, fixed order) ----
    #pragma unroll
    for (int o = 16; o; o >>= 1) {
        st += __shfl_xor_sync(0xffffffffu, st, o);
        sr += __shfl_xor_sync(0xffffffffu, sr, o);
    }

    __shared__ float sst[NT / 32];
    __shared__ float ssr[NT / 32];
    __shared__ bool  s_last;
    int lane = threadIdx.x & 31;
    int w    = threadIdx.x >> 5;
    if (lane == 0) { sst[w] = st; ssr[w] = sr; }
    __syncthreads();

    if (w == 0) {
        st = (lane < NT / 32) ? sst[lane] : 0.0f;
        sr = (lane < NT / 32) ? ssr[lane] : 0.0f;
        #pragma unroll
        for (int o = 4; o; o >>= 1) {
            st += __shfl_xor_sync(0xffffffffu, st, o);
            sr += __shfl_xor_sync(0xffffffffu, sr, o);
        }
        if (lane == 0) g_part[blockIdx.x] = make_double2((double)st, (double)sr);
    }

    // ---- last-block final reduction ----
    if (threadIdx.x == 0) {
        __threadfence();                              // publish g_part[bid]
        unsigned old = atomicAdd(&g_ticket, 1u);
        s_last = (old == (unsigned)(NB - 1));
    }
    __syncthreads();
    if (!s_last) return;

    if (threadIdx.x == 0) g_ticket = 0;               // reset for next replay

    double dst = 0.0, dsr = 0.0;
    for (int i = threadIdx.x; i < NB; i += NT) {
        double2 p = __ldcg(&g_part[i]);               // L2 load (skip stale L1)
        dst += p.x;
        dsr += p.y;
    }
    #pragma unroll
    for (int o = 16; o; o >>= 1) {
        dst += __shfl_xor_sync(0xffffffffu, dst, o);
        dsr += __shfl_xor_sync(0xffffffffu, dsr, o);
    }
    __shared__ double dt[NT / 32];
    __shared__ double dr[NT / 32];
    if (lane == 0) { dt[w] = dst; dr[w] = dsr; }
    __syncthreads();
    if (threadIdx.x == 0) {
        dst = 0.0; dsr = 0.0;
        #pragma unroll
        for (int i = 0; i < NT / 32; i++) { dst += dt[i]; dsr += dr[i]; }
        double cnt = (double)(ntotal / 2);            // 3 of 6 channels each
        double trans_loss = dst / cnt;
        double rot_loss   = (dsr / cnt) * 100.0;
        out[0] = (float)(trans_loss + rot_loss);
        out[1] = (float)trans_loss;
        out[2] = (float)rot_loss;
    }
}

extern "C" void kernel_launch(void* const* d_in, const int* in_sizes, int n_in,
                              void* d_out, int out_size) {
    const float4* pred = (const float4*)d_in[0];
    const float4* tgt  = (const float4*)d_in[1];
    float* out = (float*)d_out;

    long long ntotal = (long long)in_sizes[0];   // 25,165,824 (divisible by 12)
    int ngroups = (int)(ntotal / 12);            // 2,097,152 groups of 3 float4

    wmse_fused_kernel<<<NB, NT>>>(pred, tgt, out, ngroups, ntotal);
}